// round 16
// baseline (speedup 1.0000x reference)
#include <cuda_runtime.h>
#include <cuda_bf16.h>
#include <cuda_fp16.h>
#include <math.h>
#include <stdint.h>

#define BB 4
#define CC 64
#define NN 6400

// ---------------- scratch ----------------
__device__ float g_Q [BB * NN * CC];   // [b][n][c], row n = q(h=n%80, w=n/80)
__device__ float g_V [BB * NN * CC];   // [b][m][c], row m = v(h=m%80, w=m/80)
__device__ float g_Kc[BB * NN * CC];   // [b][m][c], k natural order
__device__ float g_Lp[BB * 32 * CC * CC];
__device__ float g_ma[BB * CC * CC];
// MMA tiles, ldmatrix-swizzled (all fp16)
__device__ uint4 g_Qt[BB * 100 * 512];   // fp16: [row64][ch64]
__device__ uint4 g_Kt[BB * 100 * 512];   // fp16: [key64][ch64]
__device__ uint4 g_Vt[BB * 100 * 512];   // fp16: [ch64][key64]
// split-kv partials: 800 CTAs x 128 rows; O stored fp16x2 (ch pairs)
__device__ unsigned g_Oph[800 * 128 * 32];
__device__ float g_Od[800 * 128];
__device__ float g_Om[800 * 128];

#define ONES_H2 0x3C003C00u

// ---------------- helpers ----------------
__device__ __forceinline__ unsigned smem_u32(const void* p) {
    unsigned a;
    asm("{ .reg .u64 t; cvta.to.shared.u64 t, %1; cvt.u32.u64 %0, t; }" : "=r"(a) : "l"(p));
    return a;
}
__device__ __forceinline__ void ldsm4(unsigned& r0, unsigned& r1, unsigned& r2, unsigned& r3, unsigned a) {
    asm volatile("ldmatrix.sync.aligned.m8n8.x4.shared.b16 {%0,%1,%2,%3}, [%4];"
                 : "=r"(r0), "=r"(r1), "=r"(r2), "=r"(r3) : "r"(a));
}
__device__ __forceinline__ void mma_h(float* c,
                                      unsigned a0, unsigned a1, unsigned a2, unsigned a3,
                                      unsigned b0, unsigned b1) {
    asm volatile("mma.sync.aligned.m16n8k16.row.col.f32.f16.f16.f32 "
                 "{%0,%1,%2,%3}, {%4,%5,%6,%7}, {%8,%9}, {%0,%1,%2,%3};"
                 : "+f"(c[0]), "+f"(c[1]), "+f"(c[2]), "+f"(c[3])
                 : "r"(a0), "r"(a1), "r"(a2), "r"(a3), "r"(b0), "r"(b1));
}
// first-touch variant: D = A*B + 0
__device__ __forceinline__ void mma_h_z(float* c,
                                        unsigned a0, unsigned a1, unsigned a2, unsigned a3,
                                        unsigned b0, unsigned b1) {
    asm volatile("mma.sync.aligned.m16n8k16.row.col.f32.f16.f16.f32 "
                 "{%0,%1,%2,%3}, {%4,%5,%6,%7}, {%8,%9}, {%10,%10,%10,%10};"
                 : "=f"(c[0]), "=f"(c[1]), "=f"(c[2]), "=f"(c[3])
                 : "r"(a0), "r"(a1), "r"(a2), "r"(a3), "r"(b0), "r"(b1), "f"(0.f));
}
__device__ __forceinline__ unsigned pk2h(float lo, float hi) { // f16x2, lower = lo
    unsigned r; asm("cvt.rn.f16x2.f32 %0, %1, %2;" : "=r"(r) : "f"(hi), "f"(lo)); return r;
}
__device__ __forceinline__ unsigned h2exp2(unsigned x) {       // packed 2^x
    unsigned r; asm("ex2.approx.f16x2 %0, %1;" : "=r"(r) : "r"(x)); return r;
}
__device__ __forceinline__ float ex2f(float x) {
    float r; asm("ex2.approx.ftz.f32 %0, %1;" : "=f"(r) : "f"(x)); return r;
}
__device__ __forceinline__ void cpa16(unsigned d, const void* g) {
    asm volatile("cp.async.cg.shared.global [%0], [%1], 16;" :: "r"(d), "l"(g));
}
#define CP_COMMIT() asm volatile("cp.async.commit_group;" ::: "memory")
#define CP_WAIT1()  asm volatile("cp.async.wait_group 1;" ::: "memory")
#define CP_WAIT0()  asm volatile("cp.async.wait_group 0;" ::: "memory")

// ---------------------------------------------------------------------------
// Kernel 1: 1x1 conv qkv. grid (100, 2, 4)
// ---------------------------------------------------------------------------
__global__ __launch_bounds__(256) void qkv_kernel(
    const float* __restrict__ x, const float* __restrict__ w, const float* __restrict__ bias)
{
    __shared__ float ws[64][100];
    __shared__ float xs[64][64];
    const int b = blockIdx.z, half = blockIdx.y, n0 = blockIdx.x * 64;
    const int tid = threadIdx.x, obase = half * 96;

    for (int idx = tid; idx < 96 * 64; idx += 256) {
        int o = idx >> 6, c = idx & 63;
        ws[c][o] = w[(size_t)(obase + o) * 64 + c];
    }
    for (int idx = tid; idx < 64 * 64; idx += 256) {
        int c = idx >> 6, p = idx & 63;
        xs[c][p] = x[((size_t)b * 64 + c) * NN + n0 + p];
    }
    __syncthreads();

    const int p = tid & 63, o0 = (tid >> 6) * 24;
    float acc[24];
#pragma unroll
    for (int j = 0; j < 24; j++) acc[j] = 0.f;
#pragma unroll 4
    for (int c = 0; c < 64; c++) {
        float xv = xs[c][p];
#pragma unroll
        for (int j4 = 0; j4 < 24; j4 += 4) {
            float4 wv = *(const float4*)&ws[c][o0 + j4];
            acc[j4+0] += xv * wv.x; acc[j4+1] += xv * wv.y;
            acc[j4+2] += xv * wv.z; acc[j4+3] += xv * wv.w;
        }
    }
    const int n = n0 + p, h = n / 80, wq = n % 80, nt = wq * 80 + h;
#pragma unroll
    for (int j4 = 0; j4 < 24; j4 += 4) {
        const int o = obase + o0 + j4;
        float4 v4;
        v4.x = acc[j4+0] + bias[o+0]; v4.y = acc[j4+1] + bias[o+1];
        v4.z = acc[j4+2] + bias[o+2]; v4.w = acc[j4+3] + bias[o+3];
        if (o < 64) {
            *(float4*)&g_Q[((size_t)b*NN + nt)*64 + o] = v4;
        } else if (o < 128) {
            *(float4*)&g_Kc[((size_t)b*NN + n)*64 + (o-64)] = v4;
        } else {
            *(float4*)&g_V[((size_t)b*NN + nt)*64 + (o-128)] = v4;
        }
    }
}

// ---------------------------------------------------------------------------
// repack: Q/K/V fp16 ldmatrix-swizzled. grid (100, 4).
// Single g_Q read per row serves BOTH Qt (row j) and Kt (row nt(j)).
// ---------------------------------------------------------------------------
__global__ __launch_bounds__(256) void repack_kernel() {
    const int kt = blockIdx.x, b = blockIdx.y, tid = threadIdx.x;
    uint4* dQ = g_Qt + (size_t)(b * 100 + kt) * 512;
    uint4* dV = g_Vt + (size_t)(b * 100 + kt) * 512;

    for (int u = tid; u < 512; u += 256) {
        const int r = u >> 3, cu = u & 7;
        const int du = r * 8 + (cu ^ (r & 7));
        {   // Q row j -> Qt[kt][r]; same data -> Kt at m = nt(j)
            const int j = kt * 64 + r;
            const float* s = g_Q + ((size_t)b * NN + j) * 64 + cu * 8;
            float v[8];
            *(float4*)v = *(const float4*)s; *(float4*)(v + 4) = *(const float4*)(s + 4);
            uint4 hw; unsigned* hww = (unsigned*)&hw;
#pragma unroll
            for (int i = 0; i < 4; i++) hww[i] = pk2h(v[2*i], v[2*i+1]);
            dQ[du] = hw;
            const int m = (j % 80) * 80 + j / 80;       // nt(j)
            const int rm = m & 63;
            g_Kt[(size_t)(b * 100 + (m >> 6)) * 512 + rm * 8 + (cu ^ (rm & 7))] = hw;
        }
        {   // V fp16: row = ch r, keys cu*8..cu*8+7
            const float* s = g_V + ((size_t)b * NN + kt * 64 + cu * 8) * 64 + r;
            float v[8];
#pragma unroll
            for (int j = 0; j < 8; j++) v[j] = s[j * 64];
            uint4 hw; unsigned* hww = (unsigned*)&hw;
#pragma unroll
            for (int i = 0; i < 4; i++) hww[i] = pk2h(v[2*i], v[2*i+1]);
            dV[du] = hw;
        }
    }
}

// ---------------------------------------------------------------------------
// channel attention logits. grid (32 chunks, 4 b), 256 thr
// ---------------------------------------------------------------------------
__global__ __launch_bounds__(256) void chan_logits_kernel() {
    const int b = blockIdx.y, chunk = blockIdx.x, tid = threadIdx.x;
    const int tx = tid & 15, ty = tid >> 4;
    const float* __restrict__ Kc = g_Kc + (size_t)b * NN * CC;
    const float* __restrict__ Qm = g_Q  + (size_t)b * NN * CC;
    float acc[4][4];
#pragma unroll
    for (int i = 0; i < 4; i++)
#pragma unroll
        for (int j = 0; j < 4; j++) acc[i][j] = 0.f;
    const int m0 = chunk * 200;
#pragma unroll 2
    for (int m = m0; m < m0 + 200; m++) {
        float4 kv4 = *(const float4*)(Kc + (size_t)m*64 + ty*4);
        float4 qv4 = *(const float4*)(Qm + (size_t)m*64 + tx*4);
        float kv[4] = {kv4.x, kv4.y, kv4.z, kv4.w};
        float qv[4] = {qv4.x, qv4.y, qv4.z, qv4.w};
#pragma unroll
        for (int i = 0; i < 4; i++)
#pragma unroll
            for (int j = 0; j < 4; j++) acc[i][j] += kv[i] * qv[j];
    }
    float* Lp = g_Lp + ((size_t)b*32 + chunk) * 64 * 64;
#pragma unroll
    for (int i = 0; i < 4; i++)
        *(float4*)(Lp + (size_t)(ty*4 + i)*64 + tx*4) =
            make_float4(acc[i][0], acc[i][1], acc[i][2], acc[i][3]);
}

// ---------------------------------------------------------------------------
// parallel reduce + softmax. grid (64 rows, 4 b), 64 thr (thread = column)
// ---------------------------------------------------------------------------
__global__ void chan_softmax_kernel() {
    __shared__ float red[2], rs[2];
    const int c = blockIdx.x, b = blockIdx.y, j = threadIdx.x;
    float s = 0.f;
#pragma unroll
    for (int ch = 0; ch < 32; ch++)
        s += g_Lp[(((size_t)b * 32 + ch) * 64 + c) * 64 + j];
    float m = s;
#pragma unroll
    for (int o = 16; o; o >>= 1) m = fmaxf(m, __shfl_xor_sync(0xffffffffu, m, o));
    if ((j & 31) == 0) red[j >> 5] = m;
    __syncthreads();
    m = fmaxf(red[0], red[1]);
    const float e = ex2f((s - m) * 1.4426950408889634f);
    float t = e;
#pragma unroll
    for (int o = 16; o; o >>= 1) t += __shfl_xor_sync(0xffffffffu, t, o);
    if ((j & 31) == 0) rs[j >> 5] = t;
    __syncthreads();
    g_ma[((size_t)b * 64 + c) * 64 + j] = e / (rs[0] + rs[1]);
}

// ---------------------------------------------------------------------------
// warp-MMA flash v8: 256 thr (warp=16 rows), packed-fp16 exp, ones-MMA denom.
// grid (50, 4, 4), 128 rows/CTA, 25 key-tiles of 64, 2-stage cp.async.
// smem (48KB): Qf16 [0,16K); stage s at 16K + s*16K: K(8K) V(8K)
// ---------------------------------------------------------------------------
__global__ __launch_bounds__(256, 2) void flash_wm8() {
    extern __shared__ char smc[];
    const unsigned sb = smem_u32(smc);
    const int rt = blockIdx.x, quarter = blockIdx.y, b = blockIdx.z;
    const int tid = threadIdx.x, warp = tid >> 5, lane = tid & 31;
    const int g = lane >> 2, t = lane & 3;
    const int kt0 = quarter * 25;
    const float L2E = 1.4426950408889634f;

    // ---- stage-0 prefetch (K 512 + V 512 uint4) ----
    {
        const uint4* sk = g_Kt + (size_t)(b * 100 + kt0) * 512;
        const uint4* sv = g_Vt + (size_t)(b * 100 + kt0) * 512;
        const unsigned base = sb + 16384u;
#pragma unroll
        for (int j = 0; j < 2; j++) { int i = tid + j * 256; cpa16(base + i * 16, sk + i); }
#pragma unroll
        for (int j = 0; j < 2; j++) { int i = tid + j * 256; cpa16(base + 8192u + i * 16, sv + i); }
        CP_COMMIT();
    }
    // ---- Q tiles copy (rt*2, rt*2+1 contiguous -> 1024 uint4) ----
    {
        uint4* dq = (uint4*)smc;
        const uint4* src = g_Qt + (size_t)(b * 100 + rt * 2) * 512;
#pragma unroll
        for (int i = 0; i < 4; i++) { int u = tid + i * 256; dq[u] = src[u]; }
    }

    const int subA = lane >> 3, lrA = lane & 7;
    const int rA = warp * 16 + ((subA & 1) << 3) + lrA;
    const int cbA = (subA >> 1) << 4;
    const int rB16 = ((lane >> 4) << 3) + (lane & 7);
    const int bsel = ((lane >> 3) & 1) << 4;

    float O[8][4];
#pragma unroll
    for (int nb = 0; nb < 8; nb++)
#pragma unroll
        for (int j = 0; j < 4; j++) O[nb][j] = 0.f;
    float d1 = 0.f, d2 = 0.f, m1 = -INFINITY, m2 = -INFINITY;

    for (int it = 0; it < 25; it++) {
        const unsigned koff = 16384u + (unsigned)(it & 1) * 16384u;
        const unsigned voff = koff + 8192u;
        __syncthreads();
        if (it + 1 < 25) {
            const uint4* sk = g_Kt + (size_t)(b * 100 + kt0 + it + 1) * 512;
            const uint4* sv = g_Vt + (size_t)(b * 100 + kt0 + it + 1) * 512;
            const unsigned nbase = sb + 16384u + (unsigned)((it + 1) & 1) * 16384u;
#pragma unroll
            for (int j = 0; j < 2; j++) { int i = tid + j * 256; cpa16(nbase + i * 16, sk + i); }
#pragma unroll
            for (int j = 0; j < 2; j++) { int i = tid + j * 256; cpa16(nbase + 8192u + i * 16, sv + i); }
            CP_COMMIT();
            CP_WAIT1();
        } else {
            CP_WAIT0();
        }
        __syncthreads();

        // ---- S = Q K^T (single fp16 pass, first-touch C=0) ----
        float S[8][4];
#pragma unroll
        for (int kc = 0; kc < 4; kc++) {
            const unsigned aswz = (unsigned)((kc * 32 + cbA) ^ ((rA & 7) << 4));
            unsigned q0, q1, q2, q3;
            ldsm4(q0, q1, q2, q3, sb + rA * 128 + aswz);
#pragma unroll
            for (int nbp = 0; nbp < 4; nbp++) {
                const int rB = nbp * 16 + rB16;
                const unsigned bswz = (unsigned)((kc * 32 + bsel) ^ ((rB & 7) << 4));
                unsigned k0, k1, k2, k3;
                ldsm4(k0, k1, k2, k3, sb + koff + rB * 128 + bswz);
                if (kc == 0) {
                    mma_h_z(S[2*nbp],   q0, q1, q2, q3, k0, k1);
                    mma_h_z(S[2*nbp+1], q0, q1, q2, q3, k2, k3);
                } else {
                    mma_h(S[2*nbp],   q0, q1, q2, q3, k0, k1);
                    mma_h(S[2*nbp+1], q0, q1, q2, q3, k2, k3);
                }
            }
        }

        // ---- online softmax: packed fp16 exp, denominator via ones-MMA ----
        float tm1 = -INFINITY, tm2 = -INFINITY;
#pragma unroll
        for (int nb = 0; nb < 8; nb++) {
            tm1 = fmaxf(tm1, fmaxf(S[nb][0], S[nb][1]));
            tm2 = fmaxf(tm2, fmaxf(S[nb][2], S[nb][3]));
        }
        tm1 = fmaxf(tm1, __shfl_xor_sync(0xffffffffu, tm1, 1));
        tm1 = fmaxf(tm1, __shfl_xor_sync(0xffffffffu, tm1, 2));
        tm2 = fmaxf(tm2, __shfl_xor_sync(0xffffffffu, tm2, 1));
        tm2 = fmaxf(tm2, __shfl_xor_sync(0xffffffffu, tm2, 2));
        const float m1n = fmaxf(m1, tm1), m2n = fmaxf(m2, tm2);
        const float sc1 = ex2f((m1 - m1n) * L2E), sc2 = ex2f((m2 - m2n) * L2E);
        const float b1 = m1n * L2E, b2 = m2n * L2E;
        m1 = m1n; m2 = m2n;

        unsigned Ph[4][4];
#pragma unroll
        for (int nb = 0; nb < 8; nb++) {
            unsigned p01 = pk2h(fmaf(S[nb][0], L2E, -b1), fmaf(S[nb][1], L2E, -b1));
            unsigned p23 = pk2h(fmaf(S[nb][2], L2E, -b2), fmaf(S[nb][3], L2E, -b2));
            const int kc = nb >> 1, o = (nb & 1) << 1;
            Ph[kc][o]     = h2exp2(p01);
            Ph[kc][o + 1] = h2exp2(p23);
        }
        // denominator tile-sums on tensor pipe: D = P @ ones
        float Dacc[4];
#pragma unroll
        for (int kc = 0; kc < 4; kc++) {
            if (kc == 0) mma_h_z(Dacc, Ph[0][0], Ph[0][1], Ph[0][2], Ph[0][3], ONES_H2, ONES_H2);
            else         mma_h (Dacc, Ph[kc][0], Ph[kc][1], Ph[kc][2], Ph[kc][3], ONES_H2, ONES_H2);
        }
        d1 = d1 * sc1 + Dacc[0];
        d2 = d2 * sc2 + Dacc[2];
#pragma unroll
        for (int nb = 0; nb < 8; nb++) {
            O[nb][0] *= sc1; O[nb][1] *= sc1;
            O[nb][2] *= sc2; O[nb][3] *= sc2;
        }

        // ---- O += P V (fp16) ----
#pragma unroll
        for (int kc = 0; kc < 4; kc++) {
#pragma unroll
            for (int nbp = 0; nbp < 4; nbp++) {
                const int rB = nbp * 16 + rB16;
                const unsigned bswz = (unsigned)((kc * 32 + bsel) ^ ((rB & 7) << 4));
                unsigned v0, v1, v2, v3;
                ldsm4(v0, v1, v2, v3, sb + voff + rB * 128 + bswz);
                mma_h(O[2*nbp],   Ph[kc][0], Ph[kc][1], Ph[kc][2], Ph[kc][3], v0, v1);
                mma_h(O[2*nbp+1], Ph[kc][0], Ph[kc][1], Ph[kc][2], Ph[kc][3], v2, v3);
            }
        }
    }

    // ---- epilogue: store (m, d, O-fp16); d already full row sums ----
    const int cta = (b * 4 + quarter) * 50 + rt;
    unsigned* Uh = g_Oph + (size_t)cta * 4096;
    if (t == 0) {
        g_Od[cta * 128 + warp * 16 + g]     = d1;
        g_Od[cta * 128 + warp * 16 + g + 8] = d2;
        g_Om[cta * 128 + warp * 16 + g]     = m1;
        g_Om[cta * 128 + warp * 16 + g + 8] = m2;
    }
#pragma unroll
    for (int nb = 0; nb < 8; nb++) {
        Uh[(warp * 16 + g) * 32 + nb * 4 + t]     = pk2h(O[nb][0], O[nb][1]);
        Uh[(warp * 16 + g + 8) * 32 + nb * 4 + t] = pk2h(O[nb][2], O[nb][3]);
    }
}

// ---------------------------------------------------------------------------
// fused channel-apply + spatial combine. grid (100, 4), 256 thr.
// ---------------------------------------------------------------------------
__global__ __launch_bounds__(256) void chan_spatial_kernel(float* __restrict__ out) {
    __shared__ float vs[64][64];
    __shared__ float mas[64][65];
    __shared__ float sO[64 * 65];
    __shared__ float sden[64];
    __shared__ float sw[4][64];
    const int rt64 = blockIdx.x, b = blockIdx.y, tid = threadIdx.x;
    const int tx = tid & 15, ty = tid >> 4;
    const int n0 = rt64 * 64;
    const int rtb = rt64 >> 1, ro = (rt64 & 1) * 64;
    const float L2E = 1.4426950408889634f;
    int c_q[4];
#pragma unroll
    for (int q = 0; q < 4; q++) c_q[q] = (b * 4 + q) * 50 + rtb;

    if (tid < 64) {
        float mq[4], dq[4], M = -INFINITY;
#pragma unroll
        for (int q = 0; q < 4; q++) {
            mq[q] = g_Om[c_q[q] * 128 + ro + tid];
            dq[q] = g_Od[c_q[q] * 128 + ro + tid];
            M = fmaxf(M, mq[q]);
        }
        float den = 0.f;
#pragma unroll
        for (int q = 0; q < 4; q++) {
            float wq = ex2f((mq[q] - M) * L2E);
            sw[q][tid] = wq;
            den += wq * dq[q];
        }
        sden[tid] = 1.f / den;
    }
    for (int idx = tid; idx < 4096; idx += 256) {
        int c = idx >> 6, cp = idx & 63;
        mas[cp][c] = g_ma[((size_t)b * 64 + c) * 64 + cp];
    }
    {
        int p = tid >> 2, cb = (tid & 3) * 16;
        int n = n0 + p, nt = (n % 80) * 80 + n / 80;
        const float* vp = g_V + ((size_t)b * NN + nt) * 64 + cb;
#pragma unroll
        for (int k = 0; k < 4; k++) {
            float4 v4 = *(const float4*)(vp + 4 * k);
            vs[cb+4*k+0][p] = v4.x; vs[cb+4*k+1][p] = v4.y;
            vs[cb+4*k+2][p] = v4.z; vs[cb+4*k+3][p] = v4.w;
        }
    }
    __syncthreads();

#pragma unroll
    for (int i = 0; i < 8; i++) {
        int u = tid + i * 256;
        int r = u >> 5, cp2 = u & 31;
        float s0 = 0.f, s1 = 0.f;
#pragma unroll
        for (int q = 0; q < 4; q++) {
            unsigned pk = g_Oph[(size_t)c_q[q] * 4096 + (ro + r) * 32 + cp2];
            __half2 h2 = *reinterpret_cast<__half2*>(&pk);
            float2 f = __half22float2(h2);
            s0 += sw[q][r] * f.x;
            s1 += sw[q][r] * f.y;
        }
        sO[r * 65 + cp2 * 2]     = s0 * sden[r];
        sO[r * 65 + cp2 * 2 + 1] = s1 * sden[r];
    }

    float acc[4][4];
#pragma unroll
    for (int i = 0; i < 4; i++)
#pragma unroll
        for (int j = 0; j < 4; j++) acc[i][j] = 0.f;
#pragma unroll 4
    for (int cp = 0; cp < 64; cp++) {
        float mv[4];
#pragma unroll
        for (int i = 0; i < 4; i++) mv[i] = mas[cp][ty * 4 + i];
        float4 v4 = *(const float4*)&vs[cp][tx * 4];
        float vv[4] = {v4.x, v4.y, v4.z, v4.w};
#pragma unroll
        for (int i = 0; i < 4; i++)
#pragma unroll
            for (int j = 0; j < 4; j++) acc[i][j] += mv[i] * vv[j];
    }
    __syncthreads();

#pragma unroll
    for (int i = 0; i < 4; i++) {
        const int ch = ty * 4 + i;
        float4 o4;
        o4.x = acc[i][0] + sO[(tx * 4 + 0) * 65 + ch];
        o4.y = acc[i][1] + sO[(tx * 4 + 1) * 65 + ch];
        o4.z = acc[i][2] + sO[(tx * 4 + 2) * 65 + ch];
        o4.w = acc[i][3] + sO[(tx * 4 + 3) * 65 + ch];
        *(float4*)(out + ((size_t)b * 64 + ch) * NN + n0 + tx * 4) = o4;
    }
}

// ---------------------------------------------------------------------------
extern "C" void kernel_launch(void* const* d_in, const int* in_sizes, int n_in,
                              void* d_out, int out_size)
{
    const float* x    = (const float*)d_in[0];
    const float* w    = (const float*)d_in[1];
    const float* bias = (const float*)d_in[2];
    float* out = (float*)d_out;

    const int fsm = 16384 + 2 * 16384;  // 49152 B
    cudaFuncSetAttribute(flash_wm8, cudaFuncAttributeMaxDynamicSharedMemorySize, fsm);

    qkv_kernel<<<dim3(100, 2, 4), 256>>>(x, w, bias);
    repack_kernel<<<dim3(100, 4), 256>>>();
    chan_logits_kernel<<<dim3(32, 4), 256>>>();
    chan_softmax_kernel<<<dim3(64, 4), 64>>>();
    flash_wm8<<<dim3(50, 4, 4), 256, fsm>>>();
    chan_spatial_kernel<<<dim3(100, 4), 256>>>(out);
}

// round 17
// speedup vs baseline: 1.0132x; 1.0132x over previous
#include <cuda_runtime.h>
#include <cuda_bf16.h>
#include <cuda_fp16.h>
#include <math.h>
#include <stdint.h>

#define BB 4
#define CC 64
#define NN 6400

// ---------------- scratch ----------------
__device__ float g_Q [BB * NN * CC];   // [b][n][c], row n = q(h=n%80, w=n/80)
__device__ float g_V [BB * NN * CC];   // [b][m][c], row m = v(h=m%80, w=m/80)
__device__ float g_Kc[BB * NN * CC];   // [b][m][c], k natural order
__device__ float g_Lp[BB * 32 * CC * CC];
__device__ float g_ma[BB * CC * CC];
// MMA tiles, ldmatrix-swizzled (all fp16)
__device__ uint4 g_Qt[BB * 100 * 512];   // fp16: [row64][ch64]
__device__ uint4 g_Kt[BB * 100 * 512];   // fp16: [key64][ch64]
__device__ uint4 g_Vt[BB * 100 * 512];   // fp16: [ch64][key64]
// split-kv partials: 800 CTAs x 128 rows; O stored fp16x2 (ch pairs)
__device__ unsigned g_Oph[800 * 128 * 32];
__device__ float g_Od[800 * 128];
__device__ float g_Om[800 * 128];

#define ONES_H2 0x3C003C00u

// ---------------- helpers ----------------
__device__ __forceinline__ unsigned smem_u32(const void* p) {
    unsigned a;
    asm("{ .reg .u64 t; cvta.to.shared.u64 t, %1; cvt.u32.u64 %0, t; }" : "=r"(a) : "l"(p));
    return a;
}
__device__ __forceinline__ void ldsm4(unsigned& r0, unsigned& r1, unsigned& r2, unsigned& r3, unsigned a) {
    asm volatile("ldmatrix.sync.aligned.m8n8.x4.shared.b16 {%0,%1,%2,%3}, [%4];"
                 : "=r"(r0), "=r"(r1), "=r"(r2), "=r"(r3) : "r"(a));
}
__device__ __forceinline__ void mma_h(float* c,
                                      unsigned a0, unsigned a1, unsigned a2, unsigned a3,
                                      unsigned b0, unsigned b1) {
    asm volatile("mma.sync.aligned.m16n8k16.row.col.f32.f16.f16.f32 "
                 "{%0,%1,%2,%3}, {%4,%5,%6,%7}, {%8,%9}, {%0,%1,%2,%3};"
                 : "+f"(c[0]), "+f"(c[1]), "+f"(c[2]), "+f"(c[3])
                 : "r"(a0), "r"(a1), "r"(a2), "r"(a3), "r"(b0), "r"(b1));
}
// first-touch variant: D = A*B + 0
__device__ __forceinline__ void mma_h_z(float* c,
                                        unsigned a0, unsigned a1, unsigned a2, unsigned a3,
                                        unsigned b0, unsigned b1) {
    asm volatile("mma.sync.aligned.m16n8k16.row.col.f32.f16.f16.f32 "
                 "{%0,%1,%2,%3}, {%4,%5,%6,%7}, {%8,%9}, {%10,%10,%10,%10};"
                 : "=f"(c[0]), "=f"(c[1]), "=f"(c[2]), "=f"(c[3])
                 : "r"(a0), "r"(a1), "r"(a2), "r"(a3), "r"(b0), "r"(b1), "f"(0.f));
}
__device__ __forceinline__ unsigned pk2h(float lo, float hi) { // f16x2, lower = lo
    unsigned r; asm("cvt.rn.f16x2.f32 %0, %1, %2;" : "=r"(r) : "f"(hi), "f"(lo)); return r;
}
__device__ __forceinline__ unsigned h2exp2(unsigned x) {       // packed 2^x
    unsigned r; asm("ex2.approx.f16x2 %0, %1;" : "=r"(r) : "r"(x)); return r;
}
__device__ __forceinline__ float ex2f(float x) {
    float r; asm("ex2.approx.ftz.f32 %0, %1;" : "=f"(r) : "f"(x)); return r;
}
__device__ __forceinline__ void cpa16(unsigned d, const void* g) {
    asm volatile("cp.async.cg.shared.global [%0], [%1], 16;" :: "r"(d), "l"(g));
}
#define CP_COMMIT() asm volatile("cp.async.commit_group;" ::: "memory")
#define CP_WAIT1()  asm volatile("cp.async.wait_group 1;" ::: "memory")
#define CP_WAIT0()  asm volatile("cp.async.wait_group 0;" ::: "memory")

// ---------------------------------------------------------------------------
// Kernel 1: 1x1 conv qkv. grid (100, 2, 4)
// ---------------------------------------------------------------------------
__global__ __launch_bounds__(256) void qkv_kernel(
    const float* __restrict__ x, const float* __restrict__ w, const float* __restrict__ bias)
{
    __shared__ float ws[64][100];
    __shared__ float xs[64][64];
    const int b = blockIdx.z, half = blockIdx.y, n0 = blockIdx.x * 64;
    const int tid = threadIdx.x, obase = half * 96;

    for (int idx = tid; idx < 96 * 64; idx += 256) {
        int o = idx >> 6, c = idx & 63;
        ws[c][o] = w[(size_t)(obase + o) * 64 + c];
    }
    for (int idx = tid; idx < 64 * 64; idx += 256) {
        int c = idx >> 6, p = idx & 63;
        xs[c][p] = x[((size_t)b * 64 + c) * NN + n0 + p];
    }
    __syncthreads();

    const int p = tid & 63, o0 = (tid >> 6) * 24;
    float acc[24];
#pragma unroll
    for (int j = 0; j < 24; j++) acc[j] = 0.f;
#pragma unroll 4
    for (int c = 0; c < 64; c++) {
        float xv = xs[c][p];
#pragma unroll
        for (int j4 = 0; j4 < 24; j4 += 4) {
            float4 wv = *(const float4*)&ws[c][o0 + j4];
            acc[j4+0] += xv * wv.x; acc[j4+1] += xv * wv.y;
            acc[j4+2] += xv * wv.z; acc[j4+3] += xv * wv.w;
        }
    }
    const int n = n0 + p, h = n / 80, wq = n % 80, nt = wq * 80 + h;
#pragma unroll
    for (int j4 = 0; j4 < 24; j4 += 4) {
        const int o = obase + o0 + j4;
        float4 v4;
        v4.x = acc[j4+0] + bias[o+0]; v4.y = acc[j4+1] + bias[o+1];
        v4.z = acc[j4+2] + bias[o+2]; v4.w = acc[j4+3] + bias[o+3];
        if (o < 64) {
            *(float4*)&g_Q[((size_t)b*NN + nt)*64 + o] = v4;
        } else if (o < 128) {
            *(float4*)&g_Kc[((size_t)b*NN + n)*64 + (o-64)] = v4;
        } else {
            *(float4*)&g_V[((size_t)b*NN + nt)*64 + (o-128)] = v4;
        }
    }
}

// ---------------------------------------------------------------------------
// repack: Q/K/V all single fp16, ldmatrix-swizzled. grid (100, 4)
// (r15 layout: gathered K READ, tile-local coalesced writes)
// ---------------------------------------------------------------------------
__global__ __launch_bounds__(256) void repack_kernel() {
    const int kt = blockIdx.x, b = blockIdx.y, tid = threadIdx.x;
    uint4* dQ = g_Qt + (size_t)(b * 100 + kt) * 512;
    uint4* dK = g_Kt + (size_t)(b * 100 + kt) * 512;
    uint4* dV = g_Vt + (size_t)(b * 100 + kt) * 512;

    for (int u = tid; u < 512; u += 256) {
        const int r = u >> 3, cu = u & 7;
        const int du = r * 8 + (cu ^ (r & 7));
        {   // Q
            const float* s = g_Q + ((size_t)b * NN + kt * 64 + r) * 64 + cu * 8;
            float v[8];
            *(float4*)v = *(const float4*)s; *(float4*)(v + 4) = *(const float4*)(s + 4);
            uint4 hw; unsigned* hww = (unsigned*)&hw;
#pragma unroll
            for (int i = 0; i < 4; i++) hww[i] = pk2h(v[2*i], v[2*i+1]);
            dQ[du] = hw;
        }
        {   // K: key r -> m = kt*64+r, source row nt(m)  (gathered read)
            const int m = kt * 64 + r;
            const int nt = (m % 80) * 80 + m / 80;
            const float* s = g_Q + ((size_t)b * NN + nt) * 64 + cu * 8;
            float v[8];
            *(float4*)v = *(const float4*)s; *(float4*)(v + 4) = *(const float4*)(s + 4);
            uint4 hw; unsigned* hww = (unsigned*)&hw;
#pragma unroll
            for (int i = 0; i < 4; i++) hww[i] = pk2h(v[2*i], v[2*i+1]);
            dK[du] = hw;
        }
        {   // V fp16: row = ch r, keys cu*8..cu*8+7
            const float* s = g_V + ((size_t)b * NN + kt * 64 + cu * 8) * 64 + r;
            float v[8];
#pragma unroll
            for (int j = 0; j < 8; j++) v[j] = s[j * 64];
            uint4 hw; unsigned* hww = (unsigned*)&hw;
#pragma unroll
            for (int i = 0; i < 4; i++) hww[i] = pk2h(v[2*i], v[2*i+1]);
            dV[du] = hw;
        }
    }
}

// ---------------------------------------------------------------------------
// channel attention logits. grid (32 chunks, 4 b), 256 thr
// ---------------------------------------------------------------------------
__global__ __launch_bounds__(256) void chan_logits_kernel() {
    const int b = blockIdx.y, chunk = blockIdx.x, tid = threadIdx.x;
    const int tx = tid & 15, ty = tid >> 4;
    const float* __restrict__ Kc = g_Kc + (size_t)b * NN * CC;
    const float* __restrict__ Qm = g_Q  + (size_t)b * NN * CC;
    float acc[4][4];
#pragma unroll
    for (int i = 0; i < 4; i++)
#pragma unroll
        for (int j = 0; j < 4; j++) acc[i][j] = 0.f;
    const int m0 = chunk * 200;
#pragma unroll 2
    for (int m = m0; m < m0 + 200; m++) {
        float4 kv4 = *(const float4*)(Kc + (size_t)m*64 + ty*4);
        float4 qv4 = *(const float4*)(Qm + (size_t)m*64 + tx*4);
        float kv[4] = {kv4.x, kv4.y, kv4.z, kv4.w};
        float qv[4] = {qv4.x, qv4.y, qv4.z, qv4.w};
#pragma unroll
        for (int i = 0; i < 4; i++)
#pragma unroll
            for (int j = 0; j < 4; j++) acc[i][j] += kv[i] * qv[j];
    }
    float* Lp = g_Lp + ((size_t)b*32 + chunk) * 64 * 64;
#pragma unroll
    for (int i = 0; i < 4; i++)
        *(float4*)(Lp + (size_t)(ty*4 + i)*64 + tx*4) =
            make_float4(acc[i][0], acc[i][1], acc[i][2], acc[i][3]);
}

// ---------------------------------------------------------------------------
// parallel reduce + softmax. grid (64 rows, 4 b), 64 thr (thread = column)
// ---------------------------------------------------------------------------
__global__ void chan_softmax_kernel() {
    __shared__ float red[2], rs[2];
    const int c = blockIdx.x, b = blockIdx.y, j = threadIdx.x;
    float s = 0.f;
#pragma unroll
    for (int ch = 0; ch < 32; ch++)
        s += g_Lp[(((size_t)b * 32 + ch) * 64 + c) * 64 + j];
    float m = s;
#pragma unroll
    for (int o = 16; o; o >>= 1) m = fmaxf(m, __shfl_xor_sync(0xffffffffu, m, o));
    if ((j & 31) == 0) red[j >> 5] = m;
    __syncthreads();
    m = fmaxf(red[0], red[1]);
    const float e = ex2f((s - m) * 1.4426950408889634f);
    float t = e;
#pragma unroll
    for (int o = 16; o; o >>= 1) t += __shfl_xor_sync(0xffffffffu, t, o);
    if ((j & 31) == 0) rs[j >> 5] = t;
    __syncthreads();
    g_ma[((size_t)b * 64 + c) * 64 + j] = e / (rs[0] + rs[1]);
}

// ---------------------------------------------------------------------------
// warp-MMA flash v8: 256 thr (warp=16 rows), packed-fp16 exp, ones-MMA denom.
// grid (50, 4, 4), 128 rows/CTA, 25 key-tiles of 64, 2-stage cp.async.
// smem (48KB): Qf16 [0,16K); stage s at 16K + s*16K: K(8K) V(8K)
// ---------------------------------------------------------------------------
__global__ __launch_bounds__(256, 2) void flash_wm8() {
    extern __shared__ char smc[];
    const unsigned sb = smem_u32(smc);
    const int rt = blockIdx.x, quarter = blockIdx.y, b = blockIdx.z;
    const int tid = threadIdx.x, warp = tid >> 5, lane = tid & 31;
    const int g = lane >> 2, t = lane & 3;
    const int kt0 = quarter * 25;
    const float L2E = 1.4426950408889634f;

    // ---- stage-0 prefetch (K 512 + V 512 uint4) ----
    {
        const uint4* sk = g_Kt + (size_t)(b * 100 + kt0) * 512;
        const uint4* sv = g_Vt + (size_t)(b * 100 + kt0) * 512;
        const unsigned base = sb + 16384u;
#pragma unroll
        for (int j = 0; j < 2; j++) { int i = tid + j * 256; cpa16(base + i * 16, sk + i); }
#pragma unroll
        for (int j = 0; j < 2; j++) { int i = tid + j * 256; cpa16(base + 8192u + i * 16, sv + i); }
        CP_COMMIT();
    }
    // ---- Q tiles copy (rt*2, rt*2+1 contiguous -> 1024 uint4) ----
    {
        uint4* dq = (uint4*)smc;
        const uint4* src = g_Qt + (size_t)(b * 100 + rt * 2) * 512;
#pragma unroll
        for (int i = 0; i < 4; i++) { int u = tid + i * 256; dq[u] = src[u]; }
    }

    const int subA = lane >> 3, lrA = lane & 7;
    const int rA = warp * 16 + ((subA & 1) << 3) + lrA;
    const int cbA = (subA >> 1) << 4;
    const int rB16 = ((lane >> 4) << 3) + (lane & 7);
    const int bsel = ((lane >> 3) & 1) << 4;

    float O[8][4];
#pragma unroll
    for (int nb = 0; nb < 8; nb++)
#pragma unroll
        for (int j = 0; j < 4; j++) O[nb][j] = 0.f;
    float d1 = 0.f, d2 = 0.f, m1 = -INFINITY, m2 = -INFINITY;

    for (int it = 0; it < 25; it++) {
        const unsigned koff = 16384u + (unsigned)(it & 1) * 16384u;
        const unsigned voff = koff + 8192u;
        __syncthreads();
        if (it + 1 < 25) {
            const uint4* sk = g_Kt + (size_t)(b * 100 + kt0 + it + 1) * 512;
            const uint4* sv = g_Vt + (size_t)(b * 100 + kt0 + it + 1) * 512;
            const unsigned nbase = sb + 16384u + (unsigned)((it + 1) & 1) * 16384u;
#pragma unroll
            for (int j = 0; j < 2; j++) { int i = tid + j * 256; cpa16(nbase + i * 16, sk + i); }
#pragma unroll
            for (int j = 0; j < 2; j++) { int i = tid + j * 256; cpa16(nbase + 8192u + i * 16, sv + i); }
            CP_COMMIT();
            CP_WAIT1();
        } else {
            CP_WAIT0();
        }
        __syncthreads();

        // ---- S = Q K^T (single fp16 pass, first-touch C=0) ----
        float S[8][4];
#pragma unroll
        for (int kc = 0; kc < 4; kc++) {
            const unsigned aswz = (unsigned)((kc * 32 + cbA) ^ ((rA & 7) << 4));
            unsigned q0, q1, q2, q3;
            ldsm4(q0, q1, q2, q3, sb + rA * 128 + aswz);
#pragma unroll
            for (int nbp = 0; nbp < 4; nbp++) {
                const int rB = nbp * 16 + rB16;
                const unsigned bswz = (unsigned)((kc * 32 + bsel) ^ ((rB & 7) << 4));
                unsigned k0, k1, k2, k3;
                ldsm4(k0, k1, k2, k3, sb + koff + rB * 128 + bswz);
                if (kc == 0) {
                    mma_h_z(S[2*nbp],   q0, q1, q2, q3, k0, k1);
                    mma_h_z(S[2*nbp+1], q0, q1, q2, q3, k2, k3);
                } else {
                    mma_h(S[2*nbp],   q0, q1, q2, q3, k0, k1);
                    mma_h(S[2*nbp+1], q0, q1, q2, q3, k2, k3);
                }
            }
        }

        // ---- online softmax: packed fp16 exp, denominator via ones-MMA ----
        float tm1 = -INFINITY, tm2 = -INFINITY;
#pragma unroll
        for (int nb = 0; nb < 8; nb++) {
            tm1 = fmaxf(tm1, fmaxf(S[nb][0], S[nb][1]));
            tm2 = fmaxf(tm2, fmaxf(S[nb][2], S[nb][3]));
        }
        tm1 = fmaxf(tm1, __shfl_xor_sync(0xffffffffu, tm1, 1));
        tm1 = fmaxf(tm1, __shfl_xor_sync(0xffffffffu, tm1, 2));
        tm2 = fmaxf(tm2, __shfl_xor_sync(0xffffffffu, tm2, 1));
        tm2 = fmaxf(tm2, __shfl_xor_sync(0xffffffffu, tm2, 2));
        const float m1n = fmaxf(m1, tm1), m2n = fmaxf(m2, tm2);
        const float sc1 = ex2f((m1 - m1n) * L2E), sc2 = ex2f((m2 - m2n) * L2E);
        const float b1 = m1n * L2E, b2 = m2n * L2E;
        m1 = m1n; m2 = m2n;

        unsigned Ph[4][4];
#pragma unroll
        for (int nb = 0; nb < 8; nb++) {
            unsigned p01 = pk2h(fmaf(S[nb][0], L2E, -b1), fmaf(S[nb][1], L2E, -b1));
            unsigned p23 = pk2h(fmaf(S[nb][2], L2E, -b2), fmaf(S[nb][3], L2E, -b2));
            const int kc = nb >> 1, o = (nb & 1) << 1;
            Ph[kc][o]     = h2exp2(p01);
            Ph[kc][o + 1] = h2exp2(p23);
        }
        // denominator tile-sums on tensor pipe: D = P @ ones
        float Dacc[4];
#pragma unroll
        for (int kc = 0; kc < 4; kc++) {
            if (kc == 0) mma_h_z(Dacc, Ph[0][0], Ph[0][1], Ph[0][2], Ph[0][3], ONES_H2, ONES_H2);
            else         mma_h (Dacc, Ph[kc][0], Ph[kc][1], Ph[kc][2], Ph[kc][3], ONES_H2, ONES_H2);
        }
        d1 = d1 * sc1 + Dacc[0];
        d2 = d2 * sc2 + Dacc[2];
#pragma unroll
        for (int nb = 0; nb < 8; nb++) {
            O[nb][0] *= sc1; O[nb][1] *= sc1;
            O[nb][2] *= sc2; O[nb][3] *= sc2;
        }

        // ---- O += P V (fp16) ----
#pragma unroll
        for (int kc = 0; kc < 4; kc++) {
#pragma unroll
            for (int nbp = 0; nbp < 4; nbp++) {
                const int rB = nbp * 16 + rB16;
                const unsigned bswz = (unsigned)((kc * 32 + bsel) ^ ((rB & 7) << 4));
                unsigned v0, v1, v2, v3;
                ldsm4(v0, v1, v2, v3, sb + voff + rB * 128 + bswz);
                mma_h(O[2*nbp],   Ph[kc][0], Ph[kc][1], Ph[kc][2], Ph[kc][3], v0, v1);
                mma_h(O[2*nbp+1], Ph[kc][0], Ph[kc][1], Ph[kc][2], Ph[kc][3], v2, v3);
            }
        }
    }

    // ---- epilogue: store (m, d, O-fp16); d already full row sums ----
    const int cta = (b * 4 + quarter) * 50 + rt;
    unsigned* Uh = g_Oph + (size_t)cta * 4096;
    if (t == 0) {
        g_Od[cta * 128 + warp * 16 + g]     = d1;
        g_Od[cta * 128 + warp * 16 + g + 8] = d2;
        g_Om[cta * 128 + warp * 16 + g]     = m1;
        g_Om[cta * 128 + warp * 16 + g + 8] = m2;
    }
#pragma unroll
    for (int nb = 0; nb < 8; nb++) {
        Uh[(warp * 16 + g) * 32 + nb * 4 + t]     = pk2h(O[nb][0], O[nb][1]);
        Uh[(warp * 16 + g + 8) * 32 + nb * 4 + t] = pk2h(O[nb][2], O[nb][3]);
    }
}

// ---------------------------------------------------------------------------
// fused channel-apply + spatial combine. grid (100, 4), 256 thr.
// ---------------------------------------------------------------------------
__global__ __launch_bounds__(256) void chan_spatial_kernel(float* __restrict__ out) {
    __shared__ float vs[64][64];
    __shared__ float mas[64][65];
    __shared__ float sO[64 * 65];
    __shared__ float sden[64];
    __shared__ float sw[4][64];
    const int rt64 = blockIdx.x, b = blockIdx.y, tid = threadIdx.x;
    const int tx = tid & 15, ty = tid >> 4;
    const int n0 = rt64 * 64;
    const int rtb = rt64 >> 1, ro = (rt64 & 1) * 64;
    const float L2E = 1.4426950408889634f;
    int c_q[4];
#pragma unroll
    for (int q = 0; q < 4; q++) c_q[q] = (b * 4 + q) * 50 + rtb;

    if (tid < 64) {
        float mq[4], dq[4], M = -INFINITY;
#pragma unroll
        for (int q = 0; q < 4; q++) {
            mq[q] = g_Om[c_q[q] * 128 + ro + tid];
            dq[q] = g_Od[c_q[q] * 128 + ro + tid];
            M = fmaxf(M, mq[q]);
        }
        float den = 0.f;
#pragma unroll
        for (int q = 0; q < 4; q++) {
            float wq = ex2f((mq[q] - M) * L2E);
            sw[q][tid] = wq;
            den += wq * dq[q];
        }
        sden[tid] = 1.f / den;
    }
    for (int idx = tid; idx < 4096; idx += 256) {
        int c = idx >> 6, cp = idx & 63;
        mas[cp][c] = g_ma[((size_t)b * 64 + c) * 64 + cp];
    }
    {
        int p = tid >> 2, cb = (tid & 3) * 16;
        int n = n0 + p, nt = (n % 80) * 80 + n / 80;
        const float* vp = g_V + ((size_t)b * NN + nt) * 64 + cb;
#pragma unroll
        for (int k = 0; k < 4; k++) {
            float4 v4 = *(const float4*)(vp + 4 * k);
            vs[cb+4*k+0][p] = v4.x; vs[cb+4*k+1][p] = v4.y;
            vs[cb+4*k+2][p] = v4.z; vs[cb+4*k+3][p] = v4.w;
        }
    }
    __syncthreads();

#pragma unroll
    for (int i = 0; i < 8; i++) {
        int u = tid + i * 256;
        int r = u >> 5, cp2 = u & 31;
        float s0 = 0.f, s1 = 0.f;
#pragma unroll
        for (int q = 0; q < 4; q++) {
            unsigned pk = g_Oph[(size_t)c_q[q] * 4096 + (ro + r) * 32 + cp2];
            __half2 h2 = *reinterpret_cast<__half2*>(&pk);
            float2 f = __half22float2(h2);
            s0 += sw[q][r] * f.x;
            s1 += sw[q][r] * f.y;
        }
        sO[r * 65 + cp2 * 2]     = s0 * sden[r];
        sO[r * 65 + cp2 * 2 + 1] = s1 * sden[r];
    }

    float acc[4][4];
#pragma unroll
    for (int i = 0; i < 4; i++)
#pragma unroll
        for (int j = 0; j < 4; j++) acc[i][j] = 0.f;
#pragma unroll 4
    for (int cp = 0; cp < 64; cp++) {
        float mv[4];
#pragma unroll
        for (int i = 0; i < 4; i++) mv[i] = mas[cp][ty * 4 + i];
        float4 v4 = *(const float4*)&vs[cp][tx * 4];
        float vv[4] = {v4.x, v4.y, v4.z, v4.w};
#pragma unroll
        for (int i = 0; i < 4; i++)
#pragma unroll
            for (int j = 0; j < 4; j++) acc[i][j] += mv[i] * vv[j];
    }
    __syncthreads();

#pragma unroll
    for (int i = 0; i < 4; i++) {
        const int ch = ty * 4 + i;
        float4 o4;
        o4.x = acc[i][0] + sO[(tx * 4 + 0) * 65 + ch];
        o4.y = acc[i][1] + sO[(tx * 4 + 1) * 65 + ch];
        o4.z = acc[i][2] + sO[(tx * 4 + 2) * 65 + ch];
        o4.w = acc[i][3] + sO[(tx * 4 + 3) * 65 + ch];
        *(float4*)(out + ((size_t)b * 64 + ch) * NN + n0 + tx * 4) = o4;
    }
}

// ---------------------------------------------------------------------------
extern "C" void kernel_launch(void* const* d_in, const int* in_sizes, int n_in,
                              void* d_out, int out_size)
{
    const float* x    = (const float*)d_in[0];
    const float* w    = (const float*)d_in[1];
    const float* bias = (const float*)d_in[2];
    float* out = (float*)d_out;

    const int fsm = 16384 + 2 * 16384;  // 49152 B
    cudaFuncSetAttribute(flash_wm8, cudaFuncAttributeMaxDynamicSharedMemorySize, fsm);

    qkv_kernel<<<dim3(100, 2, 4), 256>>>(x, w, bias);
    repack_kernel<<<dim3(100, 4), 256>>>();
    chan_logits_kernel<<<dim3(32, 4), 256>>>();
    chan_softmax_kernel<<<dim3(64, 4), 64>>>();
    flash_wm8<<<dim3(50, 4, 4), 256, fsm>>>();
    chan_spatial_kernel<<<dim3(100, 4), 256>>>(out);
}